// round 5
// baseline (speedup 1.0000x reference)
#include <cuda_runtime.h>
#include <cuda_bf16.h>
#include <cub/cub.cuh>
#include <cstdint>

typedef unsigned int u32;
typedef unsigned long long u64;

// Problem constants
constexpr int Bq = 2, Eq = 16, Hq = 160, Wq = 288, Nq = 12, Tq = 2;
constexpr int HW  = Hq * Wq;            // 46080
constexpr int P   = Tq * HW;            // 92160 pixels per instance
constexpr int BN  = Bq * Nq;            // 24 instances

constexpr int CHPB = 72;                // chunks per b (36 per t-frame)
constexpr int CPIX = 1280;              // pixels per chunk (HW = 36*1280)
constexpr int SCH2 = CHPB * 2;          // 144 stat partials per instance (half-chunks)

constexpr int NB  = 2048;               // histogram bins over err in [0,2]
constexpr float FXS = 4096.0f;          // fixed-point scale 2^12

constexpr int NGROUP = 3;               // instance groups in errhist
constexpr int GN = 4;                   // instances per group

constexpr int LCH = 4;                  // loss chunks per instance
constexpr int LBINS = NB / LCH;         // 512
constexpr int LTH = 128;
constexpr int LIT = LBINS / LTH;        // 4

// -------- scratch (static device globals; no runtime allocation) --------
__device__ float g_part[BN * SCH2 * 33];
__device__ float g_w2[BN * Eq];         // var
__device__ float g_w1m2[BN * Eq];       // -2*var*mean
__device__ float g_c[BN];               // sum var*mean^2
__device__ float g_cnt[BN];
// packed per-bin: (pos<<47) | (neg<<30) | fxsum   (pos,neg<=92160<2^17, sum<2^30)
__device__ u64 g_hist[BN * NB];
__device__ float g_losspart[BN * LCH];

// -------- kernel 1: stats via smem feat tile, 2 instances/warp, half tiles --
__global__ void __launch_bounds__(384) k_stats(
    const float* __restrict__ f1, const float* __restrict__ f2,
    const int* __restrict__ gt) {
    extern __shared__ float tile[];     // [Eq][CPIX] = 80KB
    int blk = blockIdx.x;
    int b = blk / CHPB, ch = blk % CHPB;
    int t = (ch >= 36) ? 1 : 0;
    int hw0 = (ch - t * 36) * CPIX;
    const float* fb = (t ? f2 : f1) + (size_t)b * Eq * HW + hw0;

    for (int k = threadIdx.x; k < Eq * CPIX; k += 384) {
        int e = k / CPIX, i = k - e * CPIX;
        tile[e * CPIX + i] = fb[(size_t)e * HW + i];
    }
    __syncthreads();

    int w = threadIdx.x >> 5, lane = threadIdx.x & 31;
    int half = w / 6;                   // 0 or 1
    int n0 = (w % 6) * 2;               // instances n0, n0+1
    int p0 = half * (CPIX / 2);

    float a[66];
#pragma unroll
    for (int q = 0; q < 66; q++) a[q] = 0.f;

    const int* gt0 = gt + ((size_t)(b * Nq + n0) * Tq + t) * HW + hw0;
    const int* gt1 = gt0 + (size_t)Tq * HW;

    for (int it = 0; it < (CPIX / 2) / 32; it++) {
        int i = p0 + it * 32 + lane;
        float m0 = (float)gt0[i];
        float m1 = (float)gt1[i];
        a[32] += m0; a[65] += m1;
#pragma unroll
        for (int e = 0; e < Eq; e++) {
            float v = tile[e * CPIX + i];
            float mv0 = m0 * v, mv1 = m1 * v;
            a[e]      += mv0;  a[16 + e] += mv0 * v;
            a[33 + e] += mv1;  a[49 + e] += mv1 * v;
        }
    }

#pragma unroll
    for (int q = 0; q < 66; q++)
#pragma unroll
        for (int off = 16; off > 0; off >>= 1)
            a[q] += __shfl_down_sync(0xFFFFFFFFu, a[q], off);

    if (lane == 0) {
        int ch2 = ch * 2 + half;
        float* d0 = &g_part[((size_t)(b * Nq + n0) * SCH2 + ch2) * 33];
        float* d1 = &g_part[((size_t)(b * Nq + n0 + 1) * SCH2 + ch2) * 33];
#pragma unroll
        for (int q = 0; q < 33; q++) { d0[q] = a[q]; d1[q] = a[33 + q]; }
    }
}

// -------- kernel 2: finalize -> w2, w1m2, c, cnt --------
__global__ void k_stats2() {
    int bn = blockIdx.x;
    __shared__ float ps[8][33];
    __shared__ float sums[33];
    __shared__ float vm2[16];
    int tid = threadIdx.x;              // 288 threads; 264 active
    if (tid < 264) {
        int grp = tid / 33, q = tid - grp * 33;
        float s = 0.f;
        for (int c = grp * 18; c < grp * 18 + 18; c++)
            s += g_part[((size_t)bn * SCH2 + c) * 33 + q];
        ps[grp][q] = s;
    }
    __syncthreads();
    if (tid < 33) {
        float s = 0.f;
#pragma unroll
        for (int g = 0; g < 8; g++) s += ps[g][tid];
        sums[tid] = s;
    }
    __syncthreads();
    float cnt = sums[32];
    if (tid < Eq) {
        float mean = sums[tid] / cnt;
        float var  = (sums[16 + tid] - cnt * mean * mean) / (cnt - 1.0f);
        g_w2[bn * Eq + tid]   = var;
        g_w1m2[bn * Eq + tid] = -2.0f * var * mean;
        vm2[tid] = var * mean * mean;
    }
    __syncthreads();
    if (tid == 0) {
        float c = 0.f;
#pragma unroll
        for (int e = 0; e < Eq; e++) c += vm2[e];
        g_c[bn] = c;
        g_cnt[bn] = cnt;
    }
}

// -------- kernel 3: fused error + histogram, 12 instances per block --------
// smem: u64 hist[Nq*NB] = 192KB, block-local packed (pos<<48)|(neg<<32)|fxsum
__global__ void __launch_bounds__(256) k_errhist(
    const float* __restrict__ f1, const float* __restrict__ f2,
    const int* __restrict__ gt) {
    extern __shared__ u64 hist[];
    int blk = blockIdx.x;
    int b = blk / CHPB, ch = blk % CHPB;
    int t = (ch >= 36) ? 1 : 0;
    int hw0 = (ch - t * 36) * CPIX;
    const float* fb = (t ? f2 : f1) + (size_t)b * Eq * HW + hw0;

    for (int i = threadIdx.x; i < Nq * NB; i += 256) hist[i] = 0ull;
    __syncthreads();

    int lane = threadIdx.x & 31;

#pragma unroll
    for (int g = 0; g < NGROUP; g++) {
        // hoist weights for 4 instances into registers
        float w2[GN][Eq], w1[GN][Eq], cc[GN];
#pragma unroll
        for (int j = 0; j < GN; j++) {
            int bn = b * Nq + g * GN + j;
#pragma unroll
            for (int e = 0; e < Eq; e++) {
                w2[j][e] = g_w2[bn * Eq + e];
                w1[j][e] = g_w1m2[bn * Eq + e];
            }
            cc[j] = g_c[bn];
        }
        // per-thread edge accumulators (pixels/thread = 5)
        u32 c0[GN], cM[GN], s0[GN], sM[GN];
#pragma unroll
        for (int j = 0; j < GN; j++) { c0[j] = cM[j] = s0[j] = sM[j] = 0u; }

        for (int i = threadIdx.x; i < CPIX; i += 256) {
            float v[Eq];
#pragma unroll
            for (int e = 0; e < Eq; e++) v[e] = fb[(size_t)e * HW + i];
#pragma unroll
            for (int j = 0; j < GN; j++) {
                int n = g * GN + j;
                int m = gt[((size_t)(b * Nq + n) * Tq + t) * HW + hw0 + i];
                float d = cc[j];
#pragma unroll
                for (int e = 0; e < Eq; e++) {
                    float tt = fmaf(v[e], w2[j][e], w1[j][e]);
                    d = fmaf(v[e], tt, d);
                }
                float logit = 2.0f * __expf(-0.5f * d) - 1.0f;
                float err = m ? (1.0f - logit) : (1.0f + logit);
                u32 fx = (u32)(err * FXS + 0.5f);
                int bin = (int)(err * (0.5f * NB));
                if (bin > NB - 1) bin = NB - 1;
                u32 pc = m ? 0x10000u : 1u;
                if (bin == 0)           { c0[j] += pc; s0[j] += fx; }
                else if (bin == NB - 1) { cM[j] += pc; sM[j] += fx; }
                else {
                    u64 add = (m ? (1ull << 48) : (1ull << 32)) | (u64)fx;
                    atomicAdd(&hist[n * NB + bin], add);
                }
            }
        }
        // flush edges: warp reduce, leader -> global (global packing)
#pragma unroll
        for (int j = 0; j < GN; j++) {
#pragma unroll
            for (int off = 16; off > 0; off >>= 1) {
                c0[j] += __shfl_down_sync(0xFFFFFFFFu, c0[j], off);
                cM[j] += __shfl_down_sync(0xFFFFFFFFu, cM[j], off);
                s0[j] += __shfl_down_sync(0xFFFFFFFFu, s0[j], off);
                sM[j] += __shfl_down_sync(0xFFFFFFFFu, sM[j], off);
            }
            if (lane == 0) {
                size_t gb = (size_t)(b * Nq + g * GN + j) * NB;
                if (c0[j])
                    atomicAdd(&g_hist[gb + 0],
                        ((u64)(c0[j] >> 16) << 47) | ((u64)(c0[j] & 0xFFFFu) << 30) | (u64)s0[j]);
                if (cM[j])
                    atomicAdd(&g_hist[gb + NB - 1],
                        ((u64)(cM[j] >> 16) << 47) | ((u64)(cM[j] & 0xFFFFu) << 30) | (u64)sM[j]);
            }
        }
    }
    __syncthreads();

    // merge block-local mid bins into global (repack 48/32 -> 47/30)
    size_t gb0 = (size_t)b * Nq * NB;
    for (int k = threadIdx.x; k < Nq * NB; k += 256) {
        u64 h = hist[k];
        if (h) {
            u32 pos = (u32)(h >> 48);
            u32 neg = (u32)(h >> 32) & 0xFFFFu;
            u32 sum = (u32)h;
            atomicAdd(&g_hist[gb0 + k],
                      ((u64)pos << 47) | ((u64)neg << 30) | (u64)sum);
        }
    }
}

// -------- kernel 4: Lovász via descending-bin scan (parallel chunks) --------
__global__ void k_losshist() {
    int bn = blockIdx.x / LCH;
    int ch = blockIdx.x % LCH;
    float gts = g_cnt[bn];
    size_t gbase = (size_t)bn * NB;

    typedef cub::BlockScan<u64, LTH> Scan;
    __shared__ typename Scan::TempStorage ts;
    __shared__ u64 wred[4];
    __shared__ u64 s_prefix;

    // prefix over descending positions before this chunk: bins [NB-ch*LBINS, NB)
    u64 acc = 0ull;                     // (pos<<32)|tot
    for (int i = NB - ch * LBINS + (int)threadIdx.x; i < NB; i += LTH) {
        u64 h = g_hist[gbase + i];
        u32 pos = (u32)(h >> 47);
        u32 neg = (u32)(h >> 30) & 0x1FFFFu;
        acc += ((u64)pos << 32) | (u64)(pos + neg);
    }
#pragma unroll
    for (int off = 16; off > 0; off >>= 1)
        acc += __shfl_down_sync(0xFFFFFFFFu, acc, off);
    int warp = threadIdx.x >> 5, lane = threadIdx.x & 31;
    if (lane == 0) wred[warp] = acc;
    __syncthreads();
    if (threadIdx.x == 0)
        s_prefix = wred[0] + wred[1] + wred[2] + wred[3];
    __syncthreads();
    u64 carry = s_prefix;

    // local chunk
    int v0 = ch * LBINS + (int)threadIdx.x * LIT;
    u32 cp[LIT], tot[LIT], fx[LIT];
    u64 tsum = 0ull;
#pragma unroll
    for (int i = 0; i < LIT; i++) {
        int bin = NB - 1 - (v0 + i);
        u64 h = g_hist[gbase + bin];
        u32 pos = (u32)(h >> 47);
        u32 neg = (u32)(h >> 30) & 0x1FFFFu;
        cp[i] = pos; tot[i] = pos + neg;
        fx[i] = (u32)(h & 0x3FFFFFFFull);
        tsum += ((u64)pos << 32) | (u64)(pos + neg);
    }

    u64 excl;
    Scan(ts).ExclusiveSum(tsum, excl);

    u64 run = carry + excl;
    float loss = 0.f;
#pragma unroll
    for (int i = 0; i < LIT; i++) {
        if (tot[i]) {
            float cA = (float)(u32)(run >> 32);
            float kA = (float)(u32)(run & 0xFFFFFFFFull);
            float cB = cA + (float)cp[i];
            float kB = kA + (float)tot[i];
            float JA = 1.0f - (gts - cA) / (gts + kA - cA);
            float JB = 1.0f - (gts - cB) / (gts + kB - cB);
            float err_rep = (float)fx[i] / (FXS * (float)tot[i]);
            loss += err_rep * (JB - JA);
        }
        run += ((u64)cp[i] << 32) | (u64)tot[i];
    }

    __shared__ float red[LTH];
    red[threadIdx.x] = loss;
    __syncthreads();
    for (int s = LTH / 2; s > 0; s >>= 1) {
        if (threadIdx.x < s) red[threadIdx.x] += red[threadIdx.x + s];
        __syncthreads();
    }
    if (threadIdx.x == 0) g_losspart[blockIdx.x] = red[0];
}

// -------- kernel 5: final deterministic average --------
__global__ void k_final(float* __restrict__ out) {
    if (threadIdx.x == 0) {
        float s = 0.f;
        for (int i = 0; i < BN * LCH; i++) s += g_losspart[i];
        out[0] = s / (float)BN;
    }
}

extern "C" void kernel_launch(void* const* d_in, const int* in_sizes, int n_in,
                              void* d_out, int out_size) {
    const float* f1 = (const float*)d_in[0];
    const float* f2 = (const float*)d_in[1];
    const int*   gt = (const int*)d_in[2];
    float* out = (float*)d_out;

    void* hs = nullptr;
    cudaGetSymbolAddress(&hs, g_hist);
    cudaMemsetAsync(hs, 0, sizeof(u64) * BN * NB);

    constexpr int SSMEM = Eq * CPIX * 4;          // 81920
    cudaFuncSetAttribute(k_stats, cudaFuncAttributeMaxDynamicSharedMemorySize, SSMEM);
    k_stats<<<Bq * CHPB, 384, SSMEM>>>(f1, f2, gt);

    k_stats2<<<BN, 288>>>();

    constexpr int ESMEM = Nq * NB * 8;            // 196608
    cudaFuncSetAttribute(k_errhist, cudaFuncAttributeMaxDynamicSharedMemorySize, ESMEM);
    k_errhist<<<Bq * CHPB, 256, ESMEM>>>(f1, f2, gt);

    k_losshist<<<BN * LCH, LTH>>>();
    k_final<<<1, 32>>>(out);
}